// round 5
// baseline (speedup 1.0000x reference)
#include <cuda_runtime.h>

// Problem constants (fixed by the reference)
#define DVOL   128
#define RES    179
#define NPROJ  10
#define PIX    (RES * RES)          // 32041
#define NPIX   (NPROJ * PIX)        // 320410
#define BW2    134                  // padded extent of zi/xi (0..133), z0 = zi-3
#define BPL2   (BW2 * BW2)          // 17956 entries per k-plane
#define ETOT   (DVOL * BPL2)        // 2,298,368 entries
#define NGRP   ((NPIX + 31) / 32)   // 10013 pixel groups of 32

// Bilinear-coefficient table (zero guard band of 3 on each side):
//   E[k][zi][xi] = ( c00, c01-c00, c10-c00, c11-c01-c10+c00 )
// with c_ab = A[z0+a][x0+b], z0 = zi-3, x0 = xi-3,
//      A[z][x] = 0.5*(vol[z][k-1][x] + vol[z][k][x])  (vol[.,-1,.] = 0),
//      A = 0 outside z,x in [0,127].
// sample = e0 + wx*e1 + wz*(e2 + wx*e3)
__device__ float4 g_E[ETOT];        // ~36.8 MB (L2-resident)

__global__ void __launch_bounds__(256) build_E_kernel(const float* __restrict__ vol) {
    int t = blockIdx.x * blockDim.x + threadIdx.x;
    if (t >= ETOT) return;
    int k   = t / BPL2;
    int rem = t - k * BPL2;
    int zi  = rem / BW2;
    int xi  = rem - zi * BW2;
    int z0  = zi - 3;
    int x0  = xi - 3;
    bool hk = (k > 0);
    int km  = hk ? k - 1 : 0;

    float c00 = 0.f, c01 = 0.f, c10 = 0.f, c11 = 0.f;
    {
        int z = z0;
        if ((unsigned)z < 128u) {
            const float* pk = vol + (z * DVOL + k)  * DVOL;
            const float* pm = vol + (z * DVOL + km) * DVOL;
            if ((unsigned)x0       < 128u) c00 = 0.5f * (__ldg(pk + x0)     + (hk ? __ldg(pm + x0)     : 0.f));
            if ((unsigned)(x0 + 1) < 128u) c01 = 0.5f * (__ldg(pk + x0 + 1) + (hk ? __ldg(pm + x0 + 1) : 0.f));
        }
    }
    {
        int z = z0 + 1;
        if ((unsigned)z < 128u) {
            const float* pk = vol + (z * DVOL + k)  * DVOL;
            const float* pm = vol + (z * DVOL + km) * DVOL;
            if ((unsigned)x0       < 128u) c10 = 0.5f * (__ldg(pk + x0)     + (hk ? __ldg(pm + x0)     : 0.f));
            if ((unsigned)(x0 + 1) < 128u) c11 = 0.5f * (__ldg(pk + x0 + 1) + (hk ? __ldg(pm + x0 + 1) : 0.f));
        }
    }
    g_E[t] = make_float4(c00, c01 - c00, c10 - c00, c11 - c01 - c10 + c00);
}

// Block = 128 threads = 32 pixels (one per lane) x 4 k-quarters (one per warp).
// Warp q integrates k in [32q, 32q+31] ∩ [kmin,kmax]; partials combined in smem.
__global__ void __launch_bounds__(128) project_kernel(
    const float* __restrict__ poses,
    const int*   __restrict__ idx,
    float*       __restrict__ out,
    int tail)
{
    __shared__ float part[4][33];

    int g = blockIdx.x;
    if (g == NGRP) {                 // dedicated tail block: write idx appendix
        for (int u = threadIdx.x; u < tail; u += 128)
            out[NPIX + u] = (u < NPROJ) ? (float)__ldg(&idx[u]) : 0.0f;
        return;
    }

    int lane = threadIdx.x & 31;
    int q    = threadIdx.x >> 5;     // k-quarter

    int p_pix = g * 32 + lane;
    bool valid = p_pix < NPIX;
    int pp  = valid ? p_pix : NPIX - 1;
    int p   = pp / PIX;
    int rem = pp - p * PIX;
    int i   = rem / RES;             // detector row (gx)
    int j   = rem - i * RES;         // detector col (gy)

    int e = __ldg(&idx[p]);
    float ex = __ldg(&poses[e * 3 + 0]);
    float ey = __ldg(&poses[e * 3 + 1]);
    float ez = __ldg(&poses[e * 3 + 2]);

    float gx = (float)i - 89.5f;
    float gy = (float)j - 89.5f;

    // Unnormalized ray; normalization cancels except in the dx weight.
    float rx = gx - ex;
    float ry = -ey;                  // detector plane is y = 0
    float rz = gy - ez;
    float n  = sqrtf(rx * rx + ry * ry + rz * rz);
    float inv_ry = 1.0f / ry;
    float dxw = fabsf(inv_ry) * n;

    // Sample position at plane k (volume index space), linear in k.
    float sz = rx * inv_ry;
    float sx = rz * inv_ry;
    float bz = fmaf(-ey, sz, ex + 63.5f);
    float bx = fmaf(-ey, sx, ez + 63.5f);

    // Restrictive trim to the window fz,fx in [-2.5, 130.5]; the 3-wide zero
    // guard band makes the inner loop branch-free and the dropped samples are
    // exactly-zero contributions (data lives in fz,fx ∈ (-1,129)).
    float lo_k = 0.0f, hi_k = 127.0f;
    {
        if (fabsf(sz) > 1e-12f) {
            float is = 1.0f / sz;
            float t0 = (-2.5f - bz) * is, t1 = (130.5f - bz) * is;
            lo_k = fmaxf(lo_k, fminf(t0, t1));
            hi_k = fminf(hi_k, fmaxf(t0, t1));
        } else if (bz < -2.5f || bz > 130.5f) { lo_k = 1.0f; hi_k = 0.0f; }
        if (fabsf(sx) > 1e-12f) {
            float is = 1.0f / sx;
            float t0 = (-2.5f - bx) * is, t1 = (130.5f - bx) * is;
            lo_k = fmaxf(lo_k, fminf(t0, t1));
            hi_k = fminf(hi_k, fmaxf(t0, t1));
        } else if (bx < -2.5f || bx > 130.5f) { lo_k = 1.0f; hi_k = 0.0f; }
    }
    int kmin = max(0, (int)ceilf(lo_k));
    int kmax = min(DVOL - 1, (int)floorf(hi_k));

    // This warp's k-quarter
    int qlo = max(kmin, q * 32);
    int qhi = min(kmax, q * 32 + 31);

    const float4* __restrict__ base = g_E;
    float accA = 0.0f, accB = 0.0f;
    int k = qlo;

    // Batched-by-4 main loop: addresses+weights, then 4 independent LDG.128s,
    // then math — keeps 4 loads in flight (MLP=4).
    for (; k + 3 <= qhi; k += 4) {
        float wzv[4], wxv[4];
        int   offv[4];
        #pragma unroll
        for (int u = 0; u < 4; ++u) {
            float kf = (float)(k + u);
            float fz = fmaf(kf, sz, bz);
            float fx = fmaf(kf, sx, bx);
            float zf = floorf(fz);
            float xf = floorf(fx);
            wzv[u] = fz - zf;
            wxv[u] = fx - xf;
            offv[u] = (k + u) * BPL2 + (int)zf * BW2 + (int)xf + (3 * BW2 + 3);
        }
        float4 cv[4];
        #pragma unroll
        for (int u = 0; u < 4; ++u) cv[u] = __ldg(base + offv[u]);
        #pragma unroll
        for (int u = 0; u < 4; ++u) {
            float t0 = fmaf(wxv[u], cv[u].y, cv[u].x);
            float t1 = fmaf(wxv[u], cv[u].w, cv[u].z);
            accA += t0;
            accB  = fmaf(wzv[u], t1, accB);
        }
    }
    for (; k <= qhi; ++k) {
        float kf = (float)k;
        float fz = fmaf(kf, sz, bz);
        float fx = fmaf(kf, sx, bx);
        float zf = floorf(fz);
        float xf = floorf(fx);
        float wz = fz - zf;
        float wx = fx - xf;
        int off = k * BPL2 + (int)zf * BW2 + (int)xf + (3 * BW2 + 3);
        float4 c = __ldg(base + off);
        float t0 = fmaf(wx, c.y, c.x);
        float t1 = fmaf(wx, c.w, c.z);
        accA += t0;
        accB  = fmaf(wz, t1, accB);
    }

    part[q][lane] = accA + accB;
    __syncthreads();

    if (q == 0 && valid) {
        float s = part[0][lane] + part[1][lane] + part[2][lane] + part[3][lane];
        out[p_pix] = s * dxw;
    }
}

extern "C" void kernel_launch(void* const* d_in, const int* in_sizes, int n_in,
                              void* d_out, int out_size) {
    const float* vol   = (const float*)d_in[0];   // I_rec: 1*1*128*128*128 f32
    const float* poses = (const float*)d_in[1];   // 50*3 f32
    const int*   idx   = (const int*)d_in[2];     // 10 i32
    float* out = (float*)d_out;

    build_E_kernel<<<(ETOT + 255) / 256, 256>>>(vol);

    int tail = out_size - NPIX;
    if (tail < 0) tail = 0;
    if (tail > 1024) tail = 1024;
    project_kernel<<<NGRP + 1, 128>>>(poses, idx, out, tail);
}

// round 6
// speedup vs baseline: 1.2221x; 1.2221x over previous
#include <cuda_runtime.h>

// Problem constants (fixed by the reference)
#define DVOL   128
#define RES    179
#define NPROJ  10
#define PIX    (RES * RES)          // 32041
#define NPIX   (NPROJ * PIX)        // 320410
#define BW2    134                  // padded extent of zi/xi (0..133), z0 = zi-3
#define BPL2   (BW2 * BW2)          // 17956 entries per k-plane
#define ETOT   (DVOL * BPL2)        // 2,298,368 entries
#define NGRP   ((NPIX + 31) / 32)   // 10013 pixel groups of 32

#define MAGIC      8388608.0f       // 2^23
#define MAGICH     8388607.5f       // 2^23 - 0.5  (floor via round(g - 0.5))

// Bilinear-coefficient table (zero guard band of 3 on each side):
//   E[k][zi][xi] = ( c00, c01-c00, c10-c00, c11-c01-c10+c00 )
// with c_ab = A[z0+a][x0+b], z0 = zi-3, x0 = xi-3,
//      A[z][x] = 0.5*(vol[z][k-1][x] + vol[z][k][x])  (vol[.,-1,.] = 0),
//      A = 0 outside z,x in [0,127].
// sample = e0 + wx*e1 + wz*(e2 + wx*e3)
__device__ float4 g_E[ETOT];        // ~36.8 MB (L2-resident)

__global__ void __launch_bounds__(256) build_E_kernel(const float* __restrict__ vol) {
    int t = blockIdx.x * blockDim.x + threadIdx.x;
    if (t >= ETOT) return;
    int k   = t / BPL2;
    int rem = t - k * BPL2;
    int zi  = rem / BW2;
    int xi  = rem - zi * BW2;
    int z0  = zi - 3;
    int x0  = xi - 3;
    bool hk = (k > 0);
    int km  = hk ? k - 1 : 0;

    float c00 = 0.f, c01 = 0.f, c10 = 0.f, c11 = 0.f;
    {
        int z = z0;
        if ((unsigned)z < 128u) {
            const float* pk = vol + (z * DVOL + k)  * DVOL;
            const float* pm = vol + (z * DVOL + km) * DVOL;
            if ((unsigned)x0       < 128u) c00 = 0.5f * (__ldg(pk + x0)     + (hk ? __ldg(pm + x0)     : 0.f));
            if ((unsigned)(x0 + 1) < 128u) c01 = 0.5f * (__ldg(pk + x0 + 1) + (hk ? __ldg(pm + x0 + 1) : 0.f));
        }
    }
    {
        int z = z0 + 1;
        if ((unsigned)z < 128u) {
            const float* pk = vol + (z * DVOL + k)  * DVOL;
            const float* pm = vol + (z * DVOL + km) * DVOL;
            if ((unsigned)x0       < 128u) c10 = 0.5f * (__ldg(pk + x0)     + (hk ? __ldg(pm + x0)     : 0.f));
            if ((unsigned)(x0 + 1) < 128u) c11 = 0.5f * (__ldg(pk + x0 + 1) + (hk ? __ldg(pm + x0 + 1) : 0.f));
        }
    }
    g_E[t] = make_float4(c00, c01 - c00, c10 - c00, c11 - c01 - c10 + c00);
}

// Block = 128 threads = 32 pixels (one per lane) x 4 k-quarters (one per warp).
__global__ void __launch_bounds__(128) project_kernel(
    const float* __restrict__ poses,
    const int*   __restrict__ idx,
    float*       __restrict__ out,
    int tail)
{
    __shared__ float part[4][33];

    int g = blockIdx.x;
    if (g == NGRP) {                 // dedicated tail block: write idx appendix
        for (int u = threadIdx.x; u < tail; u += 128)
            out[NPIX + u] = (u < NPROJ) ? (float)__ldg(&idx[u]) : 0.0f;
        return;
    }

    int lane = threadIdx.x & 31;
    int q    = threadIdx.x >> 5;     // k-quarter

    int p_pix = g * 32 + lane;
    bool valid = p_pix < NPIX;
    int pp  = valid ? p_pix : NPIX - 1;
    int p   = pp / PIX;
    int rem = pp - p * PIX;
    int i   = rem / RES;             // detector row (gx) — warp-uniform-ish
    int j   = rem - i * RES;         // detector col (gy) — contiguous per lane

    int e = __ldg(&idx[p]);
    float ex = __ldg(&poses[e * 3 + 0]);
    float ey = __ldg(&poses[e * 3 + 1]);
    float ez = __ldg(&poses[e * 3 + 2]);

    float gx = (float)i - 89.5f;
    float gy = (float)j - 89.5f;

    // Unnormalized ray; normalization cancels except in the dx weight.
    float rx = gx - ex;
    float ry = -ey;                  // detector plane is y = 0
    float rz = gy - ez;
    float n  = sqrtf(rx * rx + ry * ry + rz * rz);
    float inv_ry = __fdividef(1.0f, ry);
    float dxw = fabsf(inv_ry) * n;

    // Sample position at plane k (volume index space), linear in k.
    float sz = rx * inv_ry;
    float sx = rz * inv_ry;
    float bz = fmaf(-ey, sz, ex + 63.5f);
    float bx = fmaf(-ey, sx, ez + 63.5f);

    // Restrictive trim to fz,fx in [-2.5, 130.5]; the 3-wide zero guard band
    // makes the loop branch-free; dropped samples are exactly zero.
    float lo_k = 0.0f, hi_k = 127.0f;
    {
        if (fabsf(sz) > 1e-12f) {
            float is = __fdividef(1.0f, sz);
            float t0 = (-2.5f - bz) * is, t1 = (130.5f - bz) * is;
            lo_k = fmaxf(lo_k, fminf(t0, t1));
            hi_k = fminf(hi_k, fmaxf(t0, t1));
        } else if (bz < -2.5f || bz > 130.5f) { lo_k = 1.0f; hi_k = 0.0f; }
        if (fabsf(sx) > 1e-12f) {
            float is = __fdividef(1.0f, sx);
            float t0 = (-2.5f - bx) * is, t1 = (130.5f - bx) * is;
            lo_k = fmaxf(lo_k, fminf(t0, t1));
            hi_k = fminf(hi_k, fmaxf(t0, t1));
        } else if (bx < -2.5f || bx > 130.5f) { lo_k = 1.0f; hi_k = 0.0f; }
    }
    int kmin = max(0, (int)ceilf(lo_k));
    int kmax = min(DVOL - 1, (int)floorf(hi_k));

    // This warp's k-quarter
    int qlo = max(kmin, q * 32);
    int qhi = min(kmax, q * 32 + 31);

    // Shift coordinates by the +3 guard so fz',fx' in [0.5, 133.5].
    float bzp = bz + 3.0f;
    float bxp = bx + 3.0f;

    float accA = 0.0f, accB = 0.0f;
    const float4* __restrict__ bp = g_E + (size_t)qlo * BPL2;
    int k = qlo;

    // Batched-by-4: addresses+weights (all full-rate FADD/LOP, no converts),
    // then 4 independent LDG.128s, then math.
    for (; k + 3 <= qhi; k += 4, bp += 4 * BPL2) {
        float wzv[4], wxv[4];
        int   offv[4];
        #pragma unroll
        for (int u = 0; u < 4; ++u) {
            float kf  = (float)(k + u);
            float fzp = fmaf(kf, sz, bzp);
            float fxp = fmaf(kf, sx, bxp);
            float mz  = fzp + MAGICH;          // 2^23 + floor(fz')
            float mx  = fxp + MAGICH;
            int   ziv = __float_as_int(mz) & 0x7FFFFF;
            int   xiv = __float_as_int(mx) & 0x7FFFFF;
            wzv[u] = fzp - (mz - MAGIC);
            wxv[u] = fxp - (mx - MAGIC);
            offv[u] = ziv * BW2 + xiv;
        }
        float4 cv[4];
        #pragma unroll
        for (int u = 0; u < 4; ++u)
            cv[u] = __ldg(bp + (u * BPL2) + offv[u]);
        #pragma unroll
        for (int u = 0; u < 4; ++u) {
            float t0 = fmaf(wxv[u], cv[u].y, cv[u].x);
            float t1 = fmaf(wxv[u], cv[u].w, cv[u].z);
            accA += t0;
            accB  = fmaf(wzv[u], t1, accB);
        }
    }
    for (; k <= qhi; ++k, bp += BPL2) {
        float kf  = (float)k;
        float fzp = fmaf(kf, sz, bzp);
        float fxp = fmaf(kf, sx, bxp);
        float mz  = fzp + MAGICH;
        float mx  = fxp + MAGICH;
        int   ziv = __float_as_int(mz) & 0x7FFFFF;
        int   xiv = __float_as_int(mx) & 0x7FFFFF;
        float wz  = fzp - (mz - MAGIC);
        float wx  = fxp - (mx - MAGIC);
        float4 c  = __ldg(bp + ziv * BW2 + xiv);
        float t0 = fmaf(wx, c.y, c.x);
        float t1 = fmaf(wx, c.w, c.z);
        accA += t0;
        accB  = fmaf(wz, t1, accB);
    }

    part[q][lane] = accA + accB;
    __syncthreads();

    if (q == 0 && valid) {
        float s = part[0][lane] + part[1][lane] + part[2][lane] + part[3][lane];
        out[p_pix] = s * dxw;
    }
}

extern "C" void kernel_launch(void* const* d_in, const int* in_sizes, int n_in,
                              void* d_out, int out_size) {
    const float* vol   = (const float*)d_in[0];   // I_rec: 1*1*128*128*128 f32
    const float* poses = (const float*)d_in[1];   // 50*3 f32
    const int*   idx   = (const int*)d_in[2];     // 10 i32
    float* out = (float*)d_out;

    build_E_kernel<<<(ETOT + 255) / 256, 256>>>(vol);

    int tail = out_size - NPIX;
    if (tail < 0) tail = 0;
    if (tail > 1024) tail = 1024;
    project_kernel<<<NGRP + 1, 128>>>(poses, idx, out, tail);
}